// round 1
// baseline (speedup 1.0000x reference)
#include <cuda_runtime.h>
#include <cstddef>

// Problem constants (fixed by the benchmark)
#define NLOC 4096
#define NNEI 120
#define NI 128          // feature dim
#define ND 32           // head dim
#define NH 4            // heads
#define WKV_COLS 640    // (ND+NI)*NH
#define ATTNW_SHIFT 20.0f
#define INV_SQRT_ND 0.17677669529663688f  // 1/sqrt(32)

// ---------------- device scratch (no allocations allowed) ----------------
__device__ float g_WqT[NI * NI];          // [col][i]  (128x128)
__device__ float g_P[NI * (NH * NI)];     // P2[i][h*128+c]  (128x512)
__device__ float g_M[(NH * NI) * NI];     // M2[h*128+c][o]  (512x128)
__device__ float g_p[NLOC * NH * NI];     // p_all[l][h*128+c] (4096x512)
__device__ float g_u[NLOC * NH * NI];     // u_all[l][h*128+c] (4096x512)

// ---------------- prep kernels ----------------

// WqT[col][i] = Wq[i][col]
__global__ void transpose_wq_kernel(const float* __restrict__ Wq) {
    int idx = blockIdx.x * blockDim.x + threadIdx.x;  // 16384 threads
    if (idx >= NI * NI) return;
    int i = idx / NI, col = idx % NI;
    g_WqT[col * NI + i] = Wq[idx];
}

// P2[i][h*128+c] = (1/sqrt(ND)) * sum_d WqT[4d+h][i] * Wkv[c*640 + 4d+h]
__global__ void prep_P_kernel(const float* __restrict__ Wkv) {
    int idx = blockIdx.x * blockDim.x + threadIdx.x;  // 65536 threads
    int i = idx & 127;           // fastest -> coalesced WqT reads
    int col = idx >> 7;          // h*128+c
    int h = col >> 7;
    int c = col & 127;
    float acc = 0.f;
    #pragma unroll
    for (int d = 0; d < ND; d++) {
        acc += g_WqT[(4 * d + h) * NI + i] * Wkv[c * WKV_COLS + 4 * d + h];
    }
    g_P[i * (NH * NI) + col] = acc * INV_SQRT_ND;
}

// M2[h*128+c][o] = sum_i Wkv[c*640 + 128 + 4i + h] * Wh[(h*128+i)*128 + o]
__global__ void prep_M_kernel(const float* __restrict__ Wkv, const float* __restrict__ Wh) {
    int idx = blockIdx.x * blockDim.x + threadIdx.x;  // 65536 threads
    int o = idx & 127;           // fastest -> coalesced Wh reads
    int row = idx >> 7;          // h*128+c
    int h = row >> 7;
    int c = row & 127;
    float acc = 0.f;
    #pragma unroll 8
    for (int i = 0; i < NI; i++) {
        acc += Wkv[c * WKV_COLS + NI + 4 * i + h] * Wh[(h * NI + i) * NI + o];
    }
    g_M[row * NI + o] = acc;
}

// ---------------- generic tiled SGEMM: C(MxN) = A(MxK) @ B(KxN) [+ bias] ----------------
// BM=BN=64, BK=16, 256 threads (16x16), each thread computes 4x4.
// All dims must be multiples of 64 / 16 (true here: 4096x512x128 and 4096x128x512).
template <bool BIAS>
__global__ __launch_bounds__(256) void sgemm64_kernel(
    const float* __restrict__ A, const float* __restrict__ B,
    const float* __restrict__ bias, float* __restrict__ C,
    int M, int N, int K)
{
    __shared__ float As[16][65];
    __shared__ float Bs[16][65];
    int n0 = blockIdx.x * 64;
    int m0 = blockIdx.y * 64;
    int tid = threadIdx.x;
    int tx = tid & 15, ty = tid >> 4;
    float acc[4][4];
    #pragma unroll
    for (int i = 0; i < 4; i++)
        #pragma unroll
        for (int j = 0; j < 4; j++) acc[i][j] = 0.f;

    for (int k0 = 0; k0 < K; k0 += 16) {
        // load A tile 64x16 -> As[k][m]
        #pragma unroll
        for (int t = tid; t < 1024; t += 256) {
            int m = t >> 4, k = t & 15;
            As[k][m] = A[(size_t)(m0 + m) * K + k0 + k];
        }
        // load B tile 16x64 -> Bs[k][n]
        #pragma unroll
        for (int t = tid; t < 1024; t += 256) {
            int k = t >> 6, n = t & 63;
            Bs[k][n] = B[(size_t)(k0 + k) * N + n0 + n];
        }
        __syncthreads();
        #pragma unroll
        for (int k = 0; k < 16; k++) {
            float a[4], b[4];
            #pragma unroll
            for (int i = 0; i < 4; i++) a[i] = As[k][ty * 4 + i];
            #pragma unroll
            for (int j = 0; j < 4; j++) b[j] = Bs[k][tx * 4 + j];
            #pragma unroll
            for (int i = 0; i < 4; i++)
                #pragma unroll
                for (int j = 0; j < 4; j++) acc[i][j] += a[i] * b[j];
        }
        __syncthreads();
    }
    #pragma unroll
    for (int i = 0; i < 4; i++) {
        int m = m0 + ty * 4 + i;
        #pragma unroll
        for (int j = 0; j < 4; j++) {
            int n = n0 + tx * 4 + j;
            float v = acc[i][j];
            if (BIAS) v += bias[n];
            C[(size_t)m * N + n] = v;
        }
    }
}

// ---------------- main fused attention kernel ----------------
// One CTA per location l. 256 threads.
// smem: gg1 tile (120x128), p (512), logits (packed n*4+h), a (packed n*4+h),
//       sw (120), u partials (2x512).
#define SM_GG     0
#define SM_PS     (NNEI * NI)                 // 15360
#define SM_LOGIT  (SM_PS + 512)               // 15872
#define SM_APACK  (SM_LOGIT + 512)            // 16384
#define SM_SW     (SM_APACK + 512)            // 16896
#define SM_UPART  (SM_SW + 128)               // 17024
#define SM_TOTAL  (SM_UPART + 1024)           // 18048 floats = 72192 bytes

__global__ __launch_bounds__(256) void attn_kernel(
    const float* __restrict__ gg1, const float* __restrict__ sw)
{
    extern __shared__ float sm[];
    float* gg    = sm + SM_GG;
    float* ps    = sm + SM_PS;
    float* logit = sm + SM_LOGIT;
    float* apack = sm + SM_APACK;
    float* swv   = sm + SM_SW;
    float* upart = sm + SM_UPART;

    int l = blockIdx.x;
    int tid = threadIdx.x;
    int warp = tid >> 5, lane = tid & 31;

    // ---- loads ----
    const float4* src = (const float4*)(gg1 + (size_t)l * (NNEI * NI));
    float4* gg4 = (float4*)gg;
    #pragma unroll
    for (int j = tid; j < (NNEI * NI) / 4; j += 256) gg4[j] = src[j];
    if (tid < 128) ((float4*)ps)[tid] = ((const float4*)(g_p + (size_t)l * 512))[tid];
    if (tid < NNEI) swv[tid] = sw[(size_t)l * NNEI + tid];
    __syncthreads();

    // ---- phase B: logits[h][n] = gg1[n] . p[h]  (warp per row, 15 rows each) ----
    const float4* ps4 = (const float4*)ps;
    for (int n = warp; n < NNEI; n += 8) {
        float4 g = gg4[n * 32 + lane];
        float4 p0 = ps4[0 * 32 + lane];
        float4 p1 = ps4[1 * 32 + lane];
        float4 p2 = ps4[2 * 32 + lane];
        float4 p3 = ps4[3 * 32 + lane];
        float a0 = g.x * p0.x + g.y * p0.y + g.z * p0.z + g.w * p0.w;
        float a1 = g.x * p1.x + g.y * p1.y + g.z * p1.z + g.w * p1.w;
        float a2 = g.x * p2.x + g.y * p2.y + g.z * p2.z + g.w * p2.w;
        float a3 = g.x * p3.x + g.y * p3.y + g.z * p3.z + g.w * p3.w;
        #pragma unroll
        for (int off = 16; off; off >>= 1) {
            a0 += __shfl_xor_sync(0xffffffffu, a0, off);
            a1 += __shfl_xor_sync(0xffffffffu, a1, off);
            a2 += __shfl_xor_sync(0xffffffffu, a2, off);
            a3 += __shfl_xor_sync(0xffffffffu, a3, off);
        }
        if (lane == 0) {
            logit[n * 4 + 0] = a0;
            logit[n * 4 + 1] = a1;
            logit[n * 4 + 2] = a2;
            logit[n * 4 + 3] = a3;
        }
    }
    __syncthreads();

    // ---- softmax per head (warp per head) ----
    if (warp < NH) {
        int h = warp;
        float t[4];
        float mx = -1e30f;
        #pragma unroll
        for (int j = 0; j < 4; j++) {
            int n = lane + 32 * j;
            if (n < NNEI) {
                float s = swv[n];
                t[j] = (logit[n * 4 + h] + ATTNW_SHIFT) * s - ATTNW_SHIFT;
                mx = fmaxf(mx, t[j]);
            } else {
                t[j] = -1e30f;
            }
        }
        #pragma unroll
        for (int off = 16; off; off >>= 1)
            mx = fmaxf(mx, __shfl_xor_sync(0xffffffffu, mx, off));
        float e[4];
        float tot = 0.f;
        #pragma unroll
        for (int j = 0; j < 4; j++) {
            int n = lane + 32 * j;
            e[j] = (n < NNEI) ? __expf(t[j] - mx) : 0.f;
            tot += e[j];
        }
        #pragma unroll
        for (int off = 16; off; off >>= 1)
            tot += __shfl_xor_sync(0xffffffffu, tot, off);
        float inv = 1.f / tot;
        #pragma unroll
        for (int j = 0; j < 4; j++) {
            int n = lane + 32 * j;
            if (n < NNEI) apack[n * 4 + h] = e[j] * inv * swv[n];
        }
    }
    __syncthreads();

    // ---- phase D: u[h][c] = sum_n a[h][n] * gg1[n][c]  (split n over 2 halves) ----
    {
        int c = tid & 127;
        int half = tid >> 7;
        int n0 = half * (NNEI / 2);
        const float4* a4 = (const float4*)apack;
        float u0 = 0.f, u1 = 0.f, u2 = 0.f, u3 = 0.f;
        #pragma unroll 4
        for (int n = n0; n < n0 + NNEI / 2; n++) {
            float g = gg[n * NI + c];
            float4 a = a4[n];
            u0 += a.x * g; u1 += a.y * g; u2 += a.z * g; u3 += a.w * g;
        }
        upart[half * 512 + 0 * 128 + c] = u0;
        upart[half * 512 + 1 * 128 + c] = u1;
        upart[half * 512 + 2 * 128 + c] = u2;
        upart[half * 512 + 3 * 128 + c] = u3;
    }
    __syncthreads();

    for (int o = tid; o < 512; o += 256)
        g_u[(size_t)l * 512 + o] = upart[o] + upart[512 + o];
}

// ---------------- launch ----------------
extern "C" void kernel_launch(void* const* d_in, const int* in_sizes, int n_in,
                              void* d_out, int out_size) {
    const float* g1  = (const float*)d_in[0];   // (4096,128)
    const float* gg1 = (const float*)d_in[1];   // (4096,120,128)
    // d_in[2] = nlist_mask (unused: sw is pre-masked, off-mask logits are exactly -20
    // in both reference and this kernel, and final weights are multiplied by sw=0)
    const float* sw  = (const float*)d_in[3];   // (4096,120)
    // d_in[4] = Wq (128,128), d_in[5] = Wkv (128,640), d_in[6] = Wh (512,128), d_in[7] = bh (128)
    const float* Wq  = (const float*)d_in[4];
    const float* Wkv = (const float*)d_in[5];
    const float* Wh  = (const float*)d_in[6];
    const float* bh  = (const float*)d_in[7];
    float* out = (float*)d_out;

    static bool attr_done = false;
    if (!attr_done) {
        cudaFuncSetAttribute(attn_kernel, cudaFuncAttributeMaxDynamicSharedMemorySize,
                             SM_TOTAL * sizeof(float));
        attr_done = true;
    }

    float* P;  cudaGetSymbolAddress((void**)&P,  g_P);
    float* M;  cudaGetSymbolAddress((void**)&M,  g_M);
    float* pA; cudaGetSymbolAddress((void**)&pA, g_p);
    float* uA; cudaGetSymbolAddress((void**)&uA, g_u);

    // 1) prep: WqT, P, M
    transpose_wq_kernel<<<64, 256>>>(Wq);
    prep_P_kernel<<<256, 256>>>(Wkv);
    prep_M_kernel<<<256, 256>>>(Wkv, Wh);

    // 2) p_all = g1 @ P   (4096x512, K=128)
    sgemm64_kernel<false><<<dim3(512 / 64, NLOC / 64), 256>>>(g1, P, nullptr, pA,
                                                             NLOC, 512, NI);
    // 3) fused attention -> u_all
    attn_kernel<<<NLOC, 256, SM_TOTAL * sizeof(float)>>>(gg1, sw);

    // 4) out = u_all @ M + bh   (4096x128, K=512)
    sgemm64_kernel<true><<<dim3(NI / 64, NLOC / 64), 256>>>(uA, M, bh, out,
                                                            NLOC, NI, 512);
}

// round 2
// speedup vs baseline: 1.3038x; 1.3038x over previous
#include <cuda_runtime.h>
#include <cstddef>

// Problem constants (fixed by the benchmark)
#define NLOC 4096
#define NNEI 120
#define NI 128          // feature dim
#define ND 32           // head dim
#define NH 4            // heads
#define WKV_COLS 640    // (ND+NI)*NH
#define ATTNW_SHIFT 20.0f
#define INV_SQRT_ND 0.17677669529663688f  // 1/sqrt(32)

// ---------------- device scratch (no allocations allowed) ----------------
__device__ float g_WqT[NI * NI];          // [col][i]  (128x128)
__device__ float g_P[NI * (NH * NI)];     // P2[i][h*128+c]  (128x512)
__device__ float g_M[(NH * NI) * NI];     // M2[h*128+c][o]  (512x128)
__device__ float g_p[NLOC * NH * NI];     // p_all[l][h*128+c] (4096x512)
__device__ float g_u[NLOC * NH * NI];     // u_all[l][h*128+c] (4096x512)

// ---------------- prep kernels ----------------

__global__ void transpose_wq_kernel(const float* __restrict__ Wq) {
    int idx = blockIdx.x * blockDim.x + threadIdx.x;
    if (idx >= NI * NI) return;
    int i = idx / NI, col = idx % NI;
    g_WqT[col * NI + i] = Wq[idx];
}

// P2[i][h*128+c] = (1/sqrt(ND)) * sum_d WqT[4d+h][i] * Wkv[c*640 + 4d+h]
__global__ void prep_P_kernel(const float* __restrict__ Wkv) {
    int idx = blockIdx.x * blockDim.x + threadIdx.x;
    int i = idx & 127;
    int col = idx >> 7;
    int h = col >> 7;
    int c = col & 127;
    float acc = 0.f;
    #pragma unroll
    for (int d = 0; d < ND; d++) {
        acc += g_WqT[(4 * d + h) * NI + i] * Wkv[c * WKV_COLS + 4 * d + h];
    }
    g_P[i * (NH * NI) + col] = acc * INV_SQRT_ND;
}

// M2[h*128+c][o] = sum_i Wkv[c*640 + 128 + 4i + h] * Wh[(h*128+i)*128 + o]
__global__ void prep_M_kernel(const float* __restrict__ Wkv, const float* __restrict__ Wh) {
    int idx = blockIdx.x * blockDim.x + threadIdx.x;
    int o = idx & 127;
    int row = idx >> 7;
    int h = row >> 7;
    int c = row & 127;
    float acc = 0.f;
    #pragma unroll 8
    for (int i = 0; i < NI; i++) {
        acc += Wkv[c * WKV_COLS + NI + 4 * i + h] * Wh[(h * NI + i) * NI + o];
    }
    g_M[row * NI + o] = acc;
}

// ---------------- SGEMM 128x64x16: C(MxN) = A(MxK) @ B(KxN) ----------------
// 256 threads, each computes 8x4. M % 128 == 0, N % 64 == 0, K % 16 == 0.
template <bool BIAS>
__global__ __launch_bounds__(256) void sgemm128x64_kernel(
    const float* __restrict__ A, const float* __restrict__ B,
    const float* __restrict__ bias, float* __restrict__ C,
    int M, int N, int K)
{
    __shared__ float As[16][136];   // [k][m], 136*4B = 16B-aligned rows
    __shared__ float Bs[16][68];    // [k][n], 68*4B = 16B-aligned rows
    int n0 = blockIdx.x * 64;
    int m0 = blockIdx.y * 128;
    int tid = threadIdx.x;
    int tx = tid & 15, ty = tid >> 4;
    float acc[8][4];
    #pragma unroll
    for (int i = 0; i < 8; i++)
        #pragma unroll
        for (int j = 0; j < 4; j++) acc[i][j] = 0.f;

    for (int k0 = 0; k0 < K; k0 += 16) {
        // A tile: 128x16 = 512 float4, 2 per thread; transpose-store
        #pragma unroll
        for (int t = 0; t < 2; t++) {
            int idx = tid * 2 + t;
            int r = idx >> 2, kq = idx & 3;
            float4 v = *(const float4*)&A[(size_t)(m0 + r) * K + k0 + kq * 4];
            As[kq * 4 + 0][r] = v.x;
            As[kq * 4 + 1][r] = v.y;
            As[kq * 4 + 2][r] = v.z;
            As[kq * 4 + 3][r] = v.w;
        }
        // B tile: 16x64 = 256 float4, 1 per thread
        {
            int k = tid >> 4, nq = tid & 15;
            float4 v = *(const float4*)&B[(size_t)(k0 + k) * N + n0 + nq * 4];
            *(float4*)&Bs[k][nq * 4] = v;
        }
        __syncthreads();
        #pragma unroll
        for (int k = 0; k < 16; k++) {
            float a[8], b[4];
            *(float4*)(a)     = *(const float4*)&As[k][ty * 8];
            *(float4*)(a + 4) = *(const float4*)&As[k][ty * 8 + 4];
            *(float4*)(b)     = *(const float4*)&Bs[k][tx * 4];
            #pragma unroll
            for (int i = 0; i < 8; i++)
                #pragma unroll
                for (int j = 0; j < 4; j++) acc[i][j] += a[i] * b[j];
        }
        __syncthreads();
    }
    float bv[4] = {0.f, 0.f, 0.f, 0.f};
    if (BIAS) {
        #pragma unroll
        for (int j = 0; j < 4; j++) bv[j] = bias[n0 + tx * 4 + j];
    }
    #pragma unroll
    for (int i = 0; i < 8; i++) {
        int m = m0 + ty * 8 + i;
        float4 v;
        v.x = acc[i][0] + bv[0];
        v.y = acc[i][1] + bv[1];
        v.z = acc[i][2] + bv[2];
        v.w = acc[i][3] + bv[3];
        *(float4*)&C[(size_t)m * N + n0 + tx * 4] = v;
    }
}

// ---------------- SGEMM 64x64x16 (for tall-skinny N=128 case) ----------------
template <bool BIAS>
__global__ __launch_bounds__(256) void sgemm64_kernel(
    const float* __restrict__ A, const float* __restrict__ B,
    const float* __restrict__ bias, float* __restrict__ C,
    int M, int N, int K)
{
    __shared__ float As[16][68];
    __shared__ float Bs[16][68];
    int n0 = blockIdx.x * 64;
    int m0 = blockIdx.y * 64;
    int tid = threadIdx.x;
    int tx = tid & 15, ty = tid >> 4;
    float acc[4][4];
    #pragma unroll
    for (int i = 0; i < 4; i++)
        #pragma unroll
        for (int j = 0; j < 4; j++) acc[i][j] = 0.f;

    for (int k0 = 0; k0 < K; k0 += 16) {
        // A tile: 64x16 = 256 float4, 1 per thread; transpose-store
        {
            int r = tid >> 2, kq = tid & 3;
            float4 v = *(const float4*)&A[(size_t)(m0 + r) * K + k0 + kq * 4];
            As[kq * 4 + 0][r] = v.x;
            As[kq * 4 + 1][r] = v.y;
            As[kq * 4 + 2][r] = v.z;
            As[kq * 4 + 3][r] = v.w;
        }
        // B tile: 16x64 = 256 float4, 1 per thread
        {
            int k = tid >> 4, nq = tid & 15;
            float4 v = *(const float4*)&B[(size_t)(k0 + k) * N + n0 + nq * 4];
            *(float4*)&Bs[k][nq * 4] = v;
        }
        __syncthreads();
        #pragma unroll
        for (int k = 0; k < 16; k++) {
            float a[4], b[4];
            *(float4*)(a) = *(const float4*)&As[k][ty * 4];
            *(float4*)(b) = *(const float4*)&Bs[k][tx * 4];
            #pragma unroll
            for (int i = 0; i < 4; i++)
                #pragma unroll
                for (int j = 0; j < 4; j++) acc[i][j] += a[i] * b[j];
        }
        __syncthreads();
    }
    float bv[4] = {0.f, 0.f, 0.f, 0.f};
    if (BIAS) {
        #pragma unroll
        for (int j = 0; j < 4; j++) bv[j] = bias[n0 + tx * 4 + j];
    }
    #pragma unroll
    for (int i = 0; i < 4; i++) {
        int m = m0 + ty * 4 + i;
        float4 v;
        v.x = acc[i][0] + bv[0];
        v.y = acc[i][1] + bv[1];
        v.z = acc[i][2] + bv[2];
        v.w = acc[i][3] + bv[3];
        *(float4*)&C[(size_t)m * N + n0 + tx * 4] = v;
    }
}

// ---------------- main fused attention kernel ----------------
// One CTA per location l. 256 threads.
#define SM_GG     0
#define SM_LOGIT  (NNEI * NI)                 // 15360
#define SM_APACK  (SM_LOGIT + 512)            // 15872
#define SM_SW     (SM_APACK + 512)            // 16384
#define SM_UPART  (SM_SW + 128)               // 16512
#define SM_TOTAL  (SM_UPART + 2048)           // 18560 floats = 74240 bytes

__global__ __launch_bounds__(256) void attn_kernel(
    const float* __restrict__ gg1, const float* __restrict__ sw)
{
    extern __shared__ float sm[];
    float* gg    = sm + SM_GG;
    float* logit = sm + SM_LOGIT;
    float* apack = sm + SM_APACK;
    float* swv   = sm + SM_SW;
    float* upart = sm + SM_UPART;

    int l = blockIdx.x;
    int tid = threadIdx.x;
    int warp = tid >> 5, lane = tid & 31;

    // ---- p for this location, held in registers per warp (global -> L1 hits) ----
    const float4* pg = (const float4*)(g_p + (size_t)l * 512);
    float4 p0 = pg[0 * 32 + lane];
    float4 p1 = pg[1 * 32 + lane];
    float4 p2 = pg[2 * 32 + lane];
    float4 p3 = pg[3 * 32 + lane];

    // ---- gg1 tile -> smem ----
    const float4* src = (const float4*)(gg1 + (size_t)l * (NNEI * NI));
    float4* gg4 = (float4*)gg;
    #pragma unroll
    for (int j = tid; j < (NNEI * NI) / 4; j += 256) gg4[j] = src[j];
    if (tid < NNEI) swv[tid] = sw[(size_t)l * NNEI + tid];
    __syncthreads();

    // ---- phase B: logits[n][h] = gg1[n] . p[h] ----
    for (int n = warp; n < NNEI; n += 8) {
        float4 g = gg4[n * 32 + lane];
        float a0 = g.x * p0.x + g.y * p0.y + g.z * p0.z + g.w * p0.w;
        float a1 = g.x * p1.x + g.y * p1.y + g.z * p1.z + g.w * p1.w;
        float a2 = g.x * p2.x + g.y * p2.y + g.z * p2.z + g.w * p2.w;
        float a3 = g.x * p3.x + g.y * p3.y + g.z * p3.z + g.w * p3.w;
        // multi-value butterfly: 6 shuffles instead of 20
        bool o1 = lane & 1, o2 = lane & 2;
        float s01 = (o1 ? a1 : a0) + __shfl_xor_sync(0xffffffffu, o1 ? a0 : a1, 1);
        float s23 = (o1 ? a3 : a2) + __shfl_xor_sync(0xffffffffu, o1 ? a2 : a3, 1);
        float s = (o2 ? s23 : s01) + __shfl_xor_sync(0xffffffffu, o2 ? s01 : s23, 2);
        s += __shfl_xor_sync(0xffffffffu, s, 4);
        s += __shfl_xor_sync(0xffffffffu, s, 8);
        s += __shfl_xor_sync(0xffffffffu, s, 16);
        // lane&3 == head index, all groups hold full sum
        if (lane < 4) logit[n * 4 + lane] = s;
    }
    __syncthreads();

    // ---- softmax per head (warp per head) ----
    if (warp < NH) {
        int h = warp;
        float t[4];
        float mx = -1e30f;
        #pragma unroll
        for (int j = 0; j < 4; j++) {
            int n = lane + 32 * j;
            if (n < NNEI) {
                float s = swv[n];
                t[j] = (logit[n * 4 + h] + ATTNW_SHIFT) * s - ATTNW_SHIFT;
                mx = fmaxf(mx, t[j]);
            } else {
                t[j] = -1e30f;
            }
        }
        #pragma unroll
        for (int off = 16; off; off >>= 1)
            mx = fmaxf(mx, __shfl_xor_sync(0xffffffffu, mx, off));
        float e[4];
        float tot = 0.f;
        #pragma unroll
        for (int j = 0; j < 4; j++) {
            int n = lane + 32 * j;
            e[j] = (n < NNEI) ? __expf(t[j] - mx) : 0.f;
            tot += e[j];
        }
        #pragma unroll
        for (int off = 16; off; off >>= 1)
            tot += __shfl_xor_sync(0xffffffffu, tot, off);
        float inv = 1.f / tot;
        #pragma unroll
        for (int j = 0; j < 4; j++) {
            int n = lane + 32 * j;
            if (n < NNEI) apack[n * 4 + h] = e[j] * inv * swv[n];
        }
    }
    __syncthreads();

    // ---- phase D: u[h][c] = sum_n a[h][n] * gg1[n][c], 4-way n split ----
    {
        int cp = (tid & 63) * 2;   // c pair
        int q  = tid >> 6;         // quarter 0..3
        int n0 = q * (NNEI / 4);
        const float4* a4 = (const float4*)apack;
        float u0x = 0.f, u0y = 0.f, u1x = 0.f, u1y = 0.f;
        float u2x = 0.f, u2y = 0.f, u3x = 0.f, u3y = 0.f;
        #pragma unroll 5
        for (int n = n0; n < n0 + NNEI / 4; n++) {
            float2 g = *(const float2*)&gg[n * NI + cp];
            float4 a = a4[n];
            u0x += a.x * g.x; u0y += a.x * g.y;
            u1x += a.y * g.x; u1y += a.y * g.y;
            u2x += a.z * g.x; u2y += a.z * g.y;
            u3x += a.w * g.x; u3y += a.w * g.y;
        }
        float* up = upart + q * 512;
        *(float2*)&up[0 * 128 + cp] = make_float2(u0x, u0y);
        *(float2*)&up[1 * 128 + cp] = make_float2(u1x, u1y);
        *(float2*)&up[2 * 128 + cp] = make_float2(u2x, u2y);
        *(float2*)&up[3 * 128 + cp] = make_float2(u3x, u3y);
    }
    __syncthreads();

    #pragma unroll
    for (int o = tid; o < 512; o += 256)
        g_u[(size_t)l * 512 + o] =
            upart[o] + upart[512 + o] + upart[1024 + o] + upart[1536 + o];
}

// ---------------- launch ----------------
extern "C" void kernel_launch(void* const* d_in, const int* in_sizes, int n_in,
                              void* d_out, int out_size) {
    const float* g1  = (const float*)d_in[0];   // (4096,128)
    const float* gg1 = (const float*)d_in[1];   // (4096,120,128)
    // d_in[2] = nlist_mask (unused: sw is pre-masked; off-mask logits are exactly -20
    // in both reference and this kernel, and final weights are multiplied by sw=0)
    const float* sw  = (const float*)d_in[3];   // (4096,120)
    const float* Wq  = (const float*)d_in[4];   // (128,128)
    const float* Wkv = (const float*)d_in[5];   // (128,640)
    const float* Wh  = (const float*)d_in[6];   // (512,128)
    const float* bh  = (const float*)d_in[7];   // (128)
    float* out = (float*)d_out;

    static bool attr_done = false;
    if (!attr_done) {
        cudaFuncSetAttribute(attn_kernel, cudaFuncAttributeMaxDynamicSharedMemorySize,
                             SM_TOTAL * sizeof(float));
        attr_done = true;
    }

    float* P;  cudaGetSymbolAddress((void**)&P,  g_P);
    float* M;  cudaGetSymbolAddress((void**)&M,  g_M);
    float* pA; cudaGetSymbolAddress((void**)&pA, g_p);
    float* uA; cudaGetSymbolAddress((void**)&uA, g_u);

    // 1) prep: WqT, P, M
    transpose_wq_kernel<<<64, 256>>>(Wq);
    prep_P_kernel<<<256, 256>>>(Wkv);
    prep_M_kernel<<<256, 256>>>(Wkv, Wh);

    // 2) p_all = g1 @ P   (4096x512, K=128) — 256 CTAs
    sgemm128x64_kernel<false><<<dim3(512 / 64, NLOC / 128), 256>>>(g1, P, nullptr, pA,
                                                                   NLOC, 512, NI);
    // 3) fused attention -> u_all
    attn_kernel<<<NLOC, 256, SM_TOTAL * sizeof(float)>>>(gg1, sw);

    // 4) out = u_all @ M + bh   (4096x128, K=512) — 128 CTAs
    sgemm64_kernel<true><<<dim3(NI / 64, NLOC / 64), 256>>>(uA, M, bh, out,
                                                            NLOC, NI, 512);
}

// round 4
// speedup vs baseline: 1.3736x; 1.0536x over previous
#include <cuda_runtime.h>
#include <cstddef>

// Problem constants (fixed by the benchmark)
#define NLOC 4096
#define NNEI 120
#define NI 128          // feature dim
#define ND 32           // head dim
#define NH 4            // heads
#define WKV_COLS 640    // (ND+NI)*NH
#define ATTNW_SHIFT 20.0f
#define INV_SQRT_ND 0.17677669529663688f  // 1/sqrt(32)

// ---------------- device scratch (no allocations allowed) ----------------
__device__ float g_WqT[NI * NI];              // [col][i]  (128x128)
__device__ float g_P[NI * (NH * NI)];         // P2[i][h*128+c]  (128x512)
__device__ float g_M[(NH * NI) * NI];         // M2[h*128+c][o]  (512x128)
__device__ float g_p[NLOC * NH * NI];         // p_all[l][h*128+c] (4096x512)
__device__ float g_u[NLOC * NH * NI];         // u_all[l][h*128+c] (4096x512)
__device__ float g_part[4 * NLOC * NI];       // split-K partials for GEMM2

// ---------------- prep kernels ----------------

__global__ void transpose_wq_kernel(const float* __restrict__ Wq) {
    int idx = blockIdx.x * blockDim.x + threadIdx.x;
    if (idx >= NI * NI) return;
    int i = idx / NI, col = idx % NI;
    g_WqT[col * NI + i] = Wq[idx];
}

// P2[i][h*128+c] = (1/sqrt(ND)) * sum_d WqT[4d+h][i] * Wkv[c*640 + 4d+h]
__global__ void prep_P_kernel(const float* __restrict__ Wkv) {
    int idx = blockIdx.x * blockDim.x + threadIdx.x;
    int i = idx & 127;
    int col = idx >> 7;
    int h = col >> 7;
    int c = col & 127;
    float acc = 0.f;
    #pragma unroll
    for (int d = 0; d < ND; d++) {
        acc += g_WqT[(4 * d + h) * NI + i] * Wkv[c * WKV_COLS + 4 * d + h];
    }
    g_P[i * (NH * NI) + col] = acc * INV_SQRT_ND;
}

// M2[h*128+c][o] = sum_i Wkv[c*640 + 128 + 4i + h] * Wh[(h*128+i)*128 + o]
__global__ void prep_M_kernel(const float* __restrict__ Wkv, const float* __restrict__ Wh) {
    int idx = blockIdx.x * blockDim.x + threadIdx.x;
    int o = idx & 127;
    int row = idx >> 7;
    int h = row >> 7;
    int c = row & 127;
    float acc = 0.f;
    #pragma unroll 8
    for (int i = 0; i < NI; i++) {
        acc += Wkv[c * WKV_COLS + NI + 4 * i + h] * Wh[(h * NI + i) * NI + o];
    }
    g_M[row * NI + o] = acc;
}

// ---------------- SGEMM 64x64, 128 threads, optional split-K ----------------
// C_part(z) (64x64 tile) = A[m, kBegin:kBegin+kPerSplit] @ B[kBegin:.., n]
// Each thread computes 8x4.
__global__ __launch_bounds__(128) void sgemm64x64_kernel(
    const float* __restrict__ A, const float* __restrict__ B, float* __restrict__ C,
    int lda, int ldb, int ldc, int kPerSplit, size_t partStride)
{
    __shared__ float As[16][68];   // [k][m]
    __shared__ float Bs[16][68];   // [k][n]
    int n0 = blockIdx.x * 64;
    int m0 = blockIdx.y * 64;
    int kBegin = blockIdx.z * kPerSplit;
    C += (size_t)blockIdx.z * partStride;
    int tid = threadIdx.x;
    int tx = tid & 15, ty = tid >> 4;
    float acc[8][4];
    #pragma unroll
    for (int i = 0; i < 8; i++)
        #pragma unroll
        for (int j = 0; j < 4; j++) acc[i][j] = 0.f;

    for (int k0 = kBegin; k0 < kBegin + kPerSplit; k0 += 16) {
        // A tile 64x16 = 256 float4, transpose-store
        #pragma unroll
        for (int t = 0; t < 2; t++) {
            int idx = t * 128 + tid;
            int r = idx >> 2, kq = idx & 3;
            float4 v = *(const float4*)&A[(size_t)(m0 + r) * lda + k0 + kq * 4];
            As[kq * 4 + 0][r] = v.x;
            As[kq * 4 + 1][r] = v.y;
            As[kq * 4 + 2][r] = v.z;
            As[kq * 4 + 3][r] = v.w;
        }
        // B tile 16x64 = 256 float4
        #pragma unroll
        for (int t = 0; t < 2; t++) {
            int idx = t * 128 + tid;
            int k = idx >> 4, nq = idx & 15;
            *(float4*)&Bs[k][nq * 4] = *(const float4*)&B[(size_t)(k0 + k) * ldb + n0 + nq * 4];
        }
        __syncthreads();
        #pragma unroll
        for (int k = 0; k < 16; k++) {
            float a[8], b[4];
            *(float4*)(a)     = *(const float4*)&As[k][ty * 8];
            *(float4*)(a + 4) = *(const float4*)&As[k][ty * 8 + 4];
            *(float4*)(b)     = *(const float4*)&Bs[k][tx * 4];
            #pragma unroll
            for (int i = 0; i < 8; i++)
                #pragma unroll
                for (int j = 0; j < 4; j++) acc[i][j] += a[i] * b[j];
        }
        __syncthreads();
    }
    #pragma unroll
    for (int i = 0; i < 8; i++) {
        int m = m0 + ty * 8 + i;
        float4 v;
        v.x = acc[i][0]; v.y = acc[i][1]; v.z = acc[i][2]; v.w = acc[i][3];
        *(float4*)&C[(size_t)m * ldc + n0 + tx * 4] = v;
    }
}

// out = sum of 4 split-K partials + bias (broadcast along rows of 128)
__global__ __launch_bounds__(256) void reduce_out_kernel(
    const float* __restrict__ bias, float* __restrict__ out)
{
    int i = blockIdx.x * 256 + threadIdx.x;     // float4 index; 131072 total
    float4 b = ((const float4*)bias)[i & 31];
    const float4* p = (const float4*)g_part;
    const int S = NLOC * NI / 4;                // 131072
    float4 v0 = p[i], v1 = p[i + S], v2 = p[i + 2 * S], v3 = p[i + 3 * S];
    float4 r;
    r.x = b.x + v0.x + v1.x + v2.x + v3.x;
    r.y = b.y + v0.y + v1.y + v2.y + v3.y;
    r.z = b.z + v0.z + v1.z + v2.z + v3.z;
    r.w = b.w + v0.w + v1.w + v2.w + v3.w;
    ((float4*)out)[i] = r;
}

// ---------------- main fused attention kernel ----------------
// One CTA per location l. 256 threads.
#define SM_GG     0
#define SM_LOGIT  (NNEI * NI)                 // 15360
#define SM_APACK  (SM_LOGIT + 512)            // 15872
#define SM_SW     (SM_APACK + 512)            // 16384
#define SM_UPART  (SM_SW + 128)               // 16512
#define SM_TOTAL  (SM_UPART + 2048)           // 18560 floats = 74240 bytes

__global__ __launch_bounds__(256) void attn_kernel(
    const float* __restrict__ gg1, const float* __restrict__ sw)
{
    extern __shared__ float sm[];
    float* gg    = sm + SM_GG;
    float* logit = sm + SM_LOGIT;
    float* apack = sm + SM_APACK;
    float* swv   = sm + SM_SW;
    float* upart = sm + SM_UPART;

    int l = blockIdx.x;
    int tid = threadIdx.x;
    int warp = tid >> 5, lane = tid & 31;
    int s = lane & 15;         // 16-lane channel slice: channels [8s, 8s+8)
    int rhalf = lane >> 4;     // row within pair

    // p slices held in registers: 2 float4 per head (channels [8s, 8s+8))
    const float4* pg = (const float4*)(g_p + (size_t)l * 512);
    float4 pA0 = pg[0 * 32 + s * 2], pA1 = pg[0 * 32 + s * 2 + 1];
    float4 pB0 = pg[1 * 32 + s * 2], pB1 = pg[1 * 32 + s * 2 + 1];
    float4 pC0 = pg[2 * 32 + s * 2], pC1 = pg[2 * 32 + s * 2 + 1];
    float4 pD0 = pg[3 * 32 + s * 2], pD1 = pg[3 * 32 + s * 2 + 1];

    if (tid < NNEI) swv[tid] = sw[(size_t)l * NNEI + tid];

    const float4* src = (const float4*)(gg1 + (size_t)l * (NNEI * NI));
    float4* gg4 = (float4*)gg;

    // ---- fused: load gg1 row pair from global, store to smem, compute logits ----
    // Warp handles row pairs {warp, warp+8, ...}; 16 lanes per row.
    for (int pair = warp; pair < NNEI / 2; pair += 8) {
        int r = pair * 2 + rhalf;
        float4 g0 = src[r * 32 + s * 2];
        float4 g1v = src[r * 32 + s * 2 + 1];
        gg4[r * 32 + s * 2] = g0;
        gg4[r * 32 + s * 2 + 1] = g1v;
        float a0 = g0.x*pA0.x + g0.y*pA0.y + g0.z*pA0.z + g0.w*pA0.w
                 + g1v.x*pA1.x + g1v.y*pA1.y + g1v.z*pA1.z + g1v.w*pA1.w;
        float a1 = g0.x*pB0.x + g0.y*pB0.y + g0.z*pB0.z + g0.w*pB0.w
                 + g1v.x*pB1.x + g1v.y*pB1.y + g1v.z*pB1.z + g1v.w*pB1.w;
        float a2 = g0.x*pC0.x + g0.y*pC0.y + g0.z*pC0.z + g0.w*pC0.w
                 + g1v.x*pC1.x + g1v.y*pC1.y + g1v.z*pC1.z + g1v.w*pC1.w;
        float a3 = g0.x*pD0.x + g0.y*pD0.y + g0.z*pD0.z + g0.w*pD0.w
                 + g1v.x*pD1.x + g1v.y*pD1.y + g1v.z*pD1.z + g1v.w*pD1.w;
        // packed butterfly over 16 lanes: 5 shuffles for 4 values
        bool o1 = lane & 1, o2 = lane & 2;
        float s01 = (o1 ? a1 : a0) + __shfl_xor_sync(0xffffffffu, o1 ? a0 : a1, 1);
        float s23 = (o1 ? a3 : a2) + __shfl_xor_sync(0xffffffffu, o1 ? a2 : a3, 1);
        float v = (o2 ? s23 : s01) + __shfl_xor_sync(0xffffffffu, o2 ? s01 : s23, 2);
        v += __shfl_xor_sync(0xffffffffu, v, 4);
        v += __shfl_xor_sync(0xffffffffu, v, 8);
        // lanes with s<4 hold the full 16-lane sum for head (lane&3)
        if (s < 4) logit[r * 4 + s] = v;
    }
    __syncthreads();

    // ---- softmax per head (warp per head) ----
    if (warp < NH) {
        int h = warp;
        float t[4];
        float mx = -1e30f;
        #pragma unroll
        for (int j = 0; j < 4; j++) {
            int n = lane + 32 * j;
            if (n < NNEI) {
                float sv = swv[n];
                t[j] = (logit[n * 4 + h] + ATTNW_SHIFT) * sv - ATTNW_SHIFT;
                mx = fmaxf(mx, t[j]);
            } else {
                t[j] = -1e30f;
            }
        }
        #pragma unroll
        for (int off = 16; off; off >>= 1)
            mx = fmaxf(mx, __shfl_xor_sync(0xffffffffu, mx, off));
        float e[4];
        float tot = 0.f;
        #pragma unroll
        for (int j = 0; j < 4; j++) {
            int n = lane + 32 * j;
            e[j] = (n < NNEI) ? __expf(t[j] - mx) : 0.f;
            tot += e[j];
        }
        #pragma unroll
        for (int off = 16; off; off >>= 1)
            tot += __shfl_xor_sync(0xffffffffu, tot, off);
        float inv = 1.f / tot;
        #pragma unroll
        for (int j = 0; j < 4; j++) {
            int n = lane + 32 * j;
            if (n < NNEI) apack[n * 4 + h] = e[j] * inv * swv[n];
        }
    }
    __syncthreads();

    // ---- phase D: u[h][c] = sum_n a[h][n] * gg1[n][c], 4-way n split ----
    {
        int cp = (tid & 63) * 2;   // c pair
        int q  = tid >> 6;         // quarter 0..3
        int n0 = q * (NNEI / 4);
        const float4* a4 = (const float4*)apack;
        float u0x = 0.f, u0y = 0.f, u1x = 0.f, u1y = 0.f;
        float u2x = 0.f, u2y = 0.f, u3x = 0.f, u3y = 0.f;
        #pragma unroll 5
        for (int n = n0; n < n0 + NNEI / 4; n++) {
            float2 g = *(const float2*)&gg[n * NI + cp];
            float4 a = a4[n];
            u0x += a.x * g.x; u0y += a.x * g.y;
            u1x += a.y * g.x; u1y += a.y * g.y;
            u2x += a.z * g.x; u2y += a.z * g.y;
            u3x += a.w * g.x; u3y += a.w * g.y;
        }
        float* up = upart + q * 512;
        *(float2*)&up[0 * 128 + cp] = make_float2(u0x, u0y);
        *(float2*)&up[1 * 128 + cp] = make_float2(u1x, u1y);
        *(float2*)&up[2 * 128 + cp] = make_float2(u2x, u2y);
        *(float2*)&up[3 * 128 + cp] = make_float2(u3x, u3y);
    }
    __syncthreads();

    #pragma unroll
    for (int o = tid; o < 512; o += 256)
        g_u[(size_t)l * 512 + o] =
            upart[o] + upart[512 + o] + upart[1024 + o] + upart[1536 + o];
}

// ---------------- launch ----------------
extern "C" void kernel_launch(void* const* d_in, const int* in_sizes, int n_in,
                              void* d_out, int out_size) {
    const float* g1  = (const float*)d_in[0];   // (4096,128)
    const float* gg1 = (const float*)d_in[1];   // (4096,120,128)
    // d_in[2] = nlist_mask (unused: sw is pre-masked; off-mask logits are exactly -20
    // in both reference and this kernel, and final weights are multiplied by sw=0)
    const float* sw  = (const float*)d_in[3];   // (4096,120)
    const float* Wq  = (const float*)d_in[4];   // (128,128)
    const float* Wkv = (const float*)d_in[5];   // (128,640)
    const float* Wh  = (const float*)d_in[6];   // (512,128)
    const float* bh  = (const float*)d_in[7];   // (128)
    float* out = (float*)d_out;

    static bool attr_done = false;
    if (!attr_done) {
        cudaFuncSetAttribute(attn_kernel, cudaFuncAttributeMaxDynamicSharedMemorySize,
                             SM_TOTAL * sizeof(float));
        attr_done = true;
    }

    float* P;  cudaGetSymbolAddress((void**)&P,  g_P);
    float* M;  cudaGetSymbolAddress((void**)&M,  g_M);
    float* pA; cudaGetSymbolAddress((void**)&pA, g_p);
    float* uA; cudaGetSymbolAddress((void**)&uA, g_u);
    float* pt; cudaGetSymbolAddress((void**)&pt, g_part);

    // 1) prep: WqT, P, M
    transpose_wq_kernel<<<64, 256>>>(Wq);
    prep_P_kernel<<<256, 256>>>(Wkv);
    prep_M_kernel<<<256, 256>>>(Wkv, Wh);

    // 2) p_all = g1 @ P   (4096x512, K=128) — 512 CTAs
    sgemm64x64_kernel<<<dim3(512 / 64, NLOC / 64, 1), 128>>>(
        g1, P, pA, NI, 512, 512, NI, 0);

    // 3) fused attention -> u_all
    attn_kernel<<<NLOC, 256, SM_TOTAL * sizeof(float)>>>(gg1, sw);

    // 4) out_part[z] = u_all[:, z*128:(z+1)*128] @ M[z*128:(z+1)*128, :] — 512 CTAs
    sgemm64x64_kernel<<<dim3(NI / 64, NLOC / 64, 4), 128>>>(
        uA, M, pt, 512, NI, NI, NI, (size_t)NLOC * NI);

    // 5) out = sum(parts) + bh
    reduce_out_kernel<<<(NLOC * NI / 4) / 256, 256>>>(bh, out);
}